// round 16
// baseline (speedup 1.0000x reference)
#include <cuda_runtime.h>

// LSTMNet: 3-layer LSTM (H=6, input=1), B=8192, T=512, FC head on final h2.
// Round 16: R11 skeleton (tanh cell, 5 elem/warp, 12 warps/blk, 137 blocks,
// single wave) with MIO reduction -- R11 is MIO-bound (~66 MIO ops/warp-step
// ~= 84% of wall; L1=64.4%):
//   1) h broadcast via per-subgroup SMEM slots: 1 STS + 3 LDS.64 per layer
//      (naturally-paired distinct values) instead of 12 SHFL-equivalents.
//   2) column-pair weights: fma2 pairs hold DISTINCT h values -> no (v,v)
//      duplication anywhere; 6 fma2/gate + 1 hadd FADD.
//   3) Whh0 hoisted to registers (smem-h frees the h-state regs).
// MIO/warp-step 66 -> ~42.

#define HD 6
#define TT 512
#define PK 164                 // floats per lane-k slice; 656B stride, conflict-free
#define WPB 12
#define TPB (WPB * 32)
#define HWW 90                 // h-slot floats per warp: 3 layers x 5 subs x 6
__device__ float g_packk[6 * PK];

// per-k slice layout (floats):
//  [0..24)    Whh0 col-pairs: ull idx m*4+g -> (w[g][2m], w[g][2m+1])
//  [24..28)   wx0[4]          [28..32)  b0[4]
//  [32..56)   Wih1 pairs      [56..80)  Whh1 pairs   [80..84)  b1[4]
//  [84..108)  Wih2 pairs      [108..132) Whh2 pairs  [132..136) b2[4]
//  [136] fc_w[k] (pre-halved)  [137] fc_b
// scales: sigmoid rows (i,f,o) x0.5 (tanh half-angle); tanh row (g) x1.0;
// h-consuming weights extra x0.5 (h stored doubled: 2h).

__global__ void prep_kernel(
    const float* __restrict__ Wih0, const float* __restrict__ Whh0,
    const float* __restrict__ bih0, const float* __restrict__ bhh0,
    const float* __restrict__ Wih1, const float* __restrict__ Whh1,
    const float* __restrict__ bih1, const float* __restrict__ bhh1,
    const float* __restrict__ Wih2, const float* __restrict__ Whh2,
    const float* __restrict__ bih2, const float* __restrict__ bhh2,
    const float* __restrict__ fcw, const float* __restrict__ fcb)
{
    int tid = threadIdx.x;
    if (tid < 24) {
        int k = tid / 4, g = tid % 4;
        float s  = (g == 2) ? 1.0f : 0.5f;
        float sh = s * 0.5f;                  // doubled-h compensation
        int row = g * HD + k;                 // PyTorch gate order i,f,g,o
        float* p = g_packk + k * PK;
        p[24 + g]  = Wih0[row] * s;
        p[28 + g]  = (bih0[row] + bhh0[row]) * s;
        p[80 + g]  = (bih1[row] + bhh1[row]) * s;
        p[132 + g] = (bih2[row] + bhh2[row]) * s;
        for (int m = 0; m < 3; m++) {
            int o = (m * 4 + g) * 2;
            p[0   + o] = Whh0[row*HD + 2*m] * sh;  p[1   + o] = Whh0[row*HD + 2*m+1] * sh;
            p[32  + o] = Wih1[row*HD + 2*m] * sh;  p[33  + o] = Wih1[row*HD + 2*m+1] * sh;
            p[56  + o] = Whh1[row*HD + 2*m] * sh;  p[57  + o] = Whh1[row*HD + 2*m+1] * sh;
            p[84  + o] = Wih2[row*HD + 2*m] * sh;  p[85  + o] = Wih2[row*HD + 2*m+1] * sh;
            p[108 + o] = Whh2[row*HD + 2*m] * sh;  p[109 + o] = Whh2[row*HD + 2*m+1] * sh;
        }
    }
    if (tid < 6) {
        g_packk[tid * PK + 136] = fcw[tid] * 0.5f;
        g_packk[tid * PK + 137] = fcb[0];
    }
}

typedef unsigned long long ull;

__device__ __forceinline__ void fma2(ull& d, ull a, ull b, ull c) {
    asm("fma.rn.f32x2 %0, %1, %2, %3;" : "=l"(d) : "l"(a), "l"(b), "l"(c));
}
__device__ __forceinline__ void mul2(ull& d, ull a, ull b) {
    asm("mul.rn.f32x2 %0, %1, %2;" : "=l"(d) : "l"(a), "l"(b));
}
__device__ __forceinline__ float hadd2(ull v) {
    float x, y; asm("mov.b64 {%0, %1}, %2;" : "=f"(x), "=f"(y) : "l"(v));
    return x + y;
}
__device__ __forceinline__ float tanh_ap(float x) {
    float y; asm("tanh.approx.f32 %0, %1;" : "=f"(y) : "f"(x)); return y;
}

// gates prescaled (zi/2, zf/2, zg, zo/2); c true; h returned DOUBLED (2h)
__device__ __forceinline__ void cell4(float zi, float zf, float zg, float zo,
                                      float& c, float& h2x)
{
    float ti = tanh_ap(zi);
    float tf = tanh_ap(zf);
    float tg = tanh_ap(zg);
    float to = tanh_ap(zo);
    float A  = fmaf(tf, c, c);        // 2f*c
    float Bv = fmaf(ti, tg, tg);      // 2i*g
    c = (A + Bv) * 0.5f;
    float th = tanh_ap(c);
    h2x = fmaf(to, th, th);           // 2h
}

__global__ void __launch_bounds__(TPB, 1)
lstm6_kernel(const float* __restrict__ x, float* __restrict__ out, int B)
{
    __shared__ __align__(16) float sw[6 * PK];
    __shared__ __align__(16) float hs[WPB * HWW];
    for (int i = threadIdx.x; i < 6 * PK; i += TPB) sw[i] = g_packk[i];

    int wwid = threadIdx.x >> 5;
    int lane = threadIdx.x & 31;
    float* hb = hs + wwid * HWW;
    for (int i = lane; i < HWW; i += 32) hb[i] = 0.f;
    __syncthreads();

    int wid = blockIdx.x * WPB + wwid;
    if (wid * 5 >= B) return;                       // warp-uniform exit

    int sub = lane / HD;                            // 0..4 active, 5 = spare
    int k   = lane - sub * HD;
    bool act = (sub < 5);
    int sv  = act ? sub : 0;
    int sb  = sv * HD;                              // FC-head shuffle base
    int elem = wid * 5 + sv;
    bool store_ok = act && (elem < B) && (k == 0);
    if (elem >= B) elem = B - 1;                    // clamp loads only

    const float* pk = sw + k * PK;

    // hoisted: Whh0 pairs (12 ull), wx0/b0/b1/b2 scalars, fc
    ull w0r[12];
    {
        const ull* w0 = reinterpret_cast<const ull*>(pk);
#pragma unroll
        for (int i = 0; i < 12; i++) w0r[i] = w0[i];
    }
    float wx0[4], b0[4], b1[4], b2[4];
#pragma unroll
    for (int g = 0; g < 4; g++) {
        wx0[g] = pk[24 + g];
        b0[g]  = pk[28 + g];
        b1[g]  = pk[80 + g];
        b2[g]  = pk[132 + g];
    }
    float fcwk = pk[136], fcbv = pk[137];

    const ull* w1i = reinterpret_cast<const ull*>(pk + 32);   // idx m*4+g
    const ull* w1r = reinterpret_cast<const ull*>(pk + 56);
    const ull* w2i = reinterpret_cast<const ull*>(pk + 84);
    const ull* w2r = reinterpret_cast<const ull*>(pk + 108);

    // h slots: [layer][sub][6]; sub stride 6 words -> conflict-free
    float* h0p = hb + 6 * sv;
    float* h1p = hb + 30 + 6 * sv;
    float* h2p = hb + 60 + 6 * sv;

    const float4* xp = reinterpret_cast<const float4*>(x + (size_t)elem * TT);
    float c0 = 0.f, c1 = 0.f, c2 = 0.f, h2own = 0.f;

#define LOADP(P, A, Bq, C)                                              \
    {   A  = *reinterpret_cast<const ull*>(P);                          \
        Bq = *reinterpret_cast<const ull*>((P) + 2);                    \
        C  = *reinterpret_cast<const ull*>((P) + 4); }

    // matvec gate g over 6 pairs (3 input + 3 recurrent), bias-folded
#define GATE12(WI, WR, PA0, PA1, PA2, PB0, PB1, PB2, BG, G, OUTG)       \
    {   ull a_;                                                         \
        mul2(a_, (WI)[G],     PA0);                                     \
        fma2(a_, (WI)[4 + G], PA1, a_);                                 \
        fma2(a_, (WI)[8 + G], PA2, a_);                                 \
        fma2(a_, (WR)[G],     PB0, a_);                                 \
        fma2(a_, (WR)[4 + G], PB1, a_);                                 \
        fma2(a_, (WR)[8 + G], PB2, a_);                                 \
        OUTG = (BG) + hadd2(a_); }

#pragma unroll 1
    for (int t4 = 0; t4 < TT / 4; t4++) {
        float4 xq = __ldg(xp + t4);
#pragma unroll
        for (int u = 0; u < 4; u++) {
            float xt = (u == 0) ? xq.x : (u == 1) ? xq.y : (u == 2) ? xq.z : xq.w;

            // ---- layer 0: gates = (b0 + wx*x) + Whh0 @ h0(old) ----
            {
                ull p0, p1, p2;
                LOADP(h0p, p0, p1, p2);
                float ga[4];
#pragma unroll
                for (int g = 0; g < 4; g++) {
                    ull a_;
                    mul2(a_, w0r[g], p0);
                    fma2(a_, w0r[4 + g], p1, a_);
                    fma2(a_, w0r[8 + g], p2, a_);
                    ga[g] = fmaf(wx0[g], xt, b0[g]) + hadd2(a_);
                }
                float h0n;
                cell4(ga[0], ga[1], ga[2], ga[3], c0, h0n);
                if (act) h0p[k] = h0n;
            }
            __syncwarp();

            // ---- layer 1: b1 + Wih1 @ h0(new) + Whh1 @ h1(old) ----
            {
                ull q0, q1, q2, r0, r1, r2;
                LOADP(h0p, q0, q1, q2);
                LOADP(h1p, r0, r1, r2);
                float ga[4];
#pragma unroll
                for (int g = 0; g < 4; g++)
                    GATE12(w1i, w1r, q0, q1, q2, r0, r1, r2, b1[g], g, ga[g]);
                float h1n;
                cell4(ga[0], ga[1], ga[2], ga[3], c1, h1n);
                if (act) h1p[k] = h1n;
            }
            __syncwarp();

            // ---- layer 2: b2 + Wih2 @ h1(new) + Whh2 @ h2(old) ----
            {
                ull q0, q1, q2, r0, r1, r2;
                LOADP(h1p, q0, q1, q2);
                LOADP(h2p, r0, r1, r2);
                float ga[4];
#pragma unroll
                for (int g = 0; g < 4; g++)
                    GATE12(w2i, w2r, q0, q1, q2, r0, r1, r2, b2[g], g, ga[g]);
                cell4(ga[0], ga[1], ga[2], ga[3], c2, h2own);
                if (act) h2p[k] = h2own;
            }
            __syncwarp();
        }
    }

    // FC head: out[e] = sum_k (2h2[k])*(fc_w[k]/2) + fc_b
    float r = h2own * fcwk;
    float s = fcbv;
#pragma unroll
    for (int j = 0; j < HD; j++)
        s += __shfl_sync(0xffffffffu, r, sb + j);
    if (store_ok) out[elem] = s;

#undef LOADP
#undef GATE12
}

extern "C" void kernel_launch(void* const* d_in, const int* in_sizes, int n_in,
                              void* d_out, int out_size)
{
    const float* x = (const float*)d_in[0];
    int B = in_sizes[0] / TT;                  // 8192
    int warps  = (B + 4) / 5;                  // 1639
    int blocks = (warps + WPB - 1) / WPB;      // 137

    prep_kernel<<<1, 64>>>(
        (const float*)d_in[1],  (const float*)d_in[2],
        (const float*)d_in[3],  (const float*)d_in[4],
        (const float*)d_in[5],  (const float*)d_in[6],
        (const float*)d_in[7],  (const float*)d_in[8],
        (const float*)d_in[9],  (const float*)d_in[10],
        (const float*)d_in[11], (const float*)d_in[12],
        (const float*)d_in[13], (const float*)d_in[14]);

    lstm6_kernel<<<blocks, TPB>>>(x, (float*)d_out, B);
}